// round 8
// baseline (speedup 1.0000x reference)
#include <cuda_runtime.h>
#include <cuda_fp16.h>

// Problem constants
#define B_    8
#define C_    64
#define N_    4096
#define K_    16
#define OUT_  64
#define R_    128   // 2*OUT rows: [0,64) = u (=(W1-W2)x + bias), [64,128) = v (=W2 x)

#define NT_   128   // nodes per block tile
#define SW_STRIDE 130   // even (8B-aligned pairs) and ≡2 mod 32 (≤2-way STS conflict)
// sW: 64*130 floats (33.3KB) + sX2: 64*128 packed f32x2 (64KB)
#define SMEM_BYTES ((C_ * SW_STRIDE) * 4 + (C_ * NT_) * 8)   // 99,584 B

// Scratch (device global — no allocation allowed)
__device__ __half g_uvh[B_ * N_ * R_];   // [b][n][r] half: row = 256B = [u 0..63 | v 0..63]

// ---- packed f32x2 helpers (sm_100+ PTX) ------------------------------------
__device__ __forceinline__ unsigned long long pack2(float lo, float hi) {
    unsigned long long r;
    asm("mov.b64 %0, {%1, %2};" : "=l"(r) : "f"(lo), "f"(hi));
    return r;
}
__device__ __forceinline__ void unpack2(unsigned long long v, float& lo, float& hi) {
    asm("mov.b64 {%0, %1}, %2;" : "=f"(lo), "=f"(hi) : "l"(v));
}
__device__ __forceinline__ void ffma2(unsigned long long& d,
                                      unsigned long long a,
                                      unsigned long long b) {
    asm("fma.rn.f32x2 %0, %1, %2, %0;" : "+l"(d) : "l"(a), "l"(b));
}

// ---------------------------------------------------------------------------
// Kernel 1: uv[b][n][r] = sum_c Wt[c][r] * x[b][c][n] (+bias r<64), fp16 store.
// Tile 128r x 128n; thread = 4 r-pairs x 8 nodes via FFMA2.
// x-tile stored PRE-PACKED as f32x2 {x,x} (8B/value): inner loop has zero packs,
// 8 LDS + 32 FFMA2 per iter for 64 FMAs -> FFMA2-pipe bound.
// ---------------------------------------------------------------------------
__global__ void __launch_bounds__(256) gemm_uv(const float* __restrict__ x,
                                               const float* __restrict__ W,
                                               const float* __restrict__ bias) {
    extern __shared__ float dsm[];
    float (*sW)[SW_STRIDE] = (float (*)[SW_STRIDE])dsm;   // [c][r] padded fp32
    unsigned long long (*sX2)[NT_] =
        (unsigned long long (*)[NT_])(dsm + C_ * SW_STRIDE);  // [c][n] packed {x,x}

    const int b  = blockIdx.y;
    const int n0 = blockIdx.x * NT_;
    const int t  = threadIdx.x;

    // Fused weight transform (W is L2-resident after the first blocks).
    for (int lin = t; lin < C_ * OUT_; lin += 256) {
        int c = lin & 63;
        int r = lin >> 6;                 // 0..63
        float a  = W[r * 128 + c];        // W1[r][c]
        float bb = W[r * 128 + 64 + c];   // W2[r][c]
        sW[c][r]      = a - bb;
        sW[c][r + 64] = bb;
    }

    // x tile, packed {x,x} once here (moves all mov.b64 out of the hot loop).
    for (int lin = t; lin < C_ * NT_; lin += 256) {
        int c  = lin >> 7;
        int nl = lin & (NT_ - 1);
        float v = x[((b * C_ + c) * N_) + n0 + nl];
        sX2[c][nl] = pack2(v, v);
    }
    __syncthreads();

    const int tr = t & 15;
    const int tc = t >> 4;         // 0..15 -> nodes 8*tc .. 8*tc+7
    const int rb = 2 * tr;

    unsigned long long acc[4][8];
    #pragma unroll
    for (int i2 = 0; i2 < 4; i2++) {
        unsigned long long binit;
        if (i2 < 2) {
            const float2 bp = *(const float2*)&bias[rb + 32 * i2];
            binit = pack2(bp.x, bp.y);
        } else {
            binit = 0ull;
        }
        #pragma unroll
        for (int j = 0; j < 8; j++) acc[i2][j] = binit;
    }

    #pragma unroll 2
    for (int c = 0; c < 64; c++) {
        unsigned long long w2[4];
        #pragma unroll
        for (int i2 = 0; i2 < 4; i2++)
            w2[i2] = *(const unsigned long long*)&sW[c][rb + 32 * i2];  // LDS.64
        unsigned long long x2[8];
        #pragma unroll
        for (int q = 0; q < 4; q++) {
            ulonglong2 p = *(const ulonglong2*)&sX2[c][8 * tc + 2 * q]; // LDS.128 (2 packed nodes)
            x2[2 * q]     = p.x;
            x2[2 * q + 1] = p.y;
        }
        #pragma unroll
        for (int i2 = 0; i2 < 4; i2++)
            #pragma unroll
            for (int j = 0; j < 8; j++)
                ffma2(acc[i2][j], w2[i2], x2[j]);
    }

    __half* outb = g_uvh + (size_t)(b * N_ + n0) * R_;
    #pragma unroll
    for (int j = 0; j < 8; j++) {
        const int n = 8 * tc + j;
        #pragma unroll
        for (int i2 = 0; i2 < 4; i2++) {
            float lo, hi;
            unpack2(acc[i2][j], lo, hi);
            *(__half2*)(outb + n * R_ + rb + 32 * i2) = __floats2half2_rn(lo, hi);
        }
    }
}

// ---------------------------------------------------------------------------
// Kernel 2: out[b][o][n] = max_k relu( u[b][i1(k)][o] + v[b][i0(k)][o] )
// Two nodes per warp; packed-index shfl; LDG.64 gathers; half2 add/max.
// At the L2-bytes roofline (~12us) — unchanged.
// ---------------------------------------------------------------------------
__global__ void __launch_bounds__(256) gather_max(const int* __restrict__ edge,
                                                  float* __restrict__ out) {
    __shared__ float sm[OUT_][17];   // 64 x 16 nodes, pad to 17

    const int b    = blockIdx.y;
    const int n0   = blockIdx.x * 16;
    const int w    = threadIdx.x >> 5;
    const int lane = threadIdx.x & 31;
    const int h    = lane >> 4;          // 0 = node A, 1 = node B
    const int sl   = lane & 15;          // sub-lane within node group
    const int n    = n0 + 2 * w + h;

    const int e0 = edge[((0 * B_ + b) * N_ + n) * K_ + sl] & (N_ - 1);   // neighbor -> v
    const int e1 = edge[((1 * B_ + b) * N_ + n) * K_ + sl] & (N_ - 1);   // center   -> u
    const unsigned packed = (unsigned)e0 | ((unsigned)e1 << 16);

    const __half* uvb = g_uvh + (size_t)b * N_ * R_;
    const int co = 4 * sl;               // this lane's channel base (4 channels)

    __half2 m0 = __float2half2_rn(0.0f);
    __half2 m1 = __float2half2_rn(0.0f);

    #pragma unroll
    for (int kk = 0; kk < K_; kk++) {
        unsigned pk = __shfl_sync(0xffffffffu, packed, (h << 4) + kk);
        int i0 = (int)(pk & (unsigned)(N_ - 1));          // v source
        int i1 = (int)((pk >> 16) & (unsigned)(N_ - 1));  // u source
        uint2 uu = *(const uint2*)(uvb + i1 * R_ + co);         // u[co..co+3]
        uint2 vv = *(const uint2*)(uvb + i0 * R_ + 64 + co);    // v[co..co+3]
        __half2 ua = *(__half2*)&uu.x, ub = *(__half2*)&uu.y;
        __half2 va = *(__half2*)&vv.x, vb = *(__half2*)&vv.y;
        m0 = __hmax2(m0, __hadd2(ua, va));
        m1 = __hmax2(m1, __hadd2(ub, vb));
    }

    const int nl = 2 * w + h;
    float2 f0 = __half22float2(m0);
    float2 f1 = __half22float2(m1);
    sm[co + 0][nl] = f0.x;
    sm[co + 1][nl] = f0.y;
    sm[co + 2][nl] = f1.x;
    sm[co + 3][nl] = f1.y;
    __syncthreads();

    const int t = threadIdx.x;
    #pragma unroll
    for (int it = 0; it < 4; it++) {
        int lin = t + it * 256;          // 1024 values: 64 o x 16 n
        int o   = lin >> 4;
        int nn  = lin & 15;
        out[((b * OUT_ + o) * N_) + n0 + nn] = sm[o][nn];
    }
}

// ---------------------------------------------------------------------------
extern "C" void kernel_launch(void* const* d_in, const int* in_sizes, int n_in,
                              void* d_out, int out_size) {
    const float* x    = (const float*)d_in[0];
    const int*   edge = (const int*)d_in[1];
    const float* W    = (const float*)d_in[2];
    const float* bias = (const float*)d_in[3];
    float*       out  = (float*)d_out;

    cudaFuncSetAttribute(gemm_uv, cudaFuncAttributeMaxDynamicSharedMemorySize, SMEM_BYTES);

    dim3 g1(N_ / NT_, B_);
    gemm_uv<<<g1, 256, SMEM_BYTES>>>(x, W, bias);

    dim3 g2(N_ / 16, B_);
    gather_max<<<g2, 256>>>(edge, out);
}

// round 9
// speedup vs baseline: 1.3589x; 1.3589x over previous
#include <cuda_runtime.h>
#include <cuda_fp16.h>
#include <mma.h>

using namespace nvcuda;

// Problem constants
#define B_    8
#define C_    64
#define N_    4096
#define K_    16
#define OUT_  64
#define R_    128   // 2*OUT rows: [0,64) = u (=(W1-W2)x + bias), [64,128) = v (=W2 x)

#define NT_   128            // nodes per block tile
#define LDA   136            // sA: half[c][LDA]  (x^T col-major, ldm mult of 8)
#define LDB   136            // sB: half[c][LDB]  (Wt row-major c x r)
#define LDS_  136            // scratch: float[n][LDS_]
#define SMEM_BYTES (NT_ * LDS_ * 4)   // 69,632 B (scratch dominates; inputs unioned)

// Scratch (device global — no allocation allowed)
__device__ __half g_uvh[B_ * N_ * R_];   // [b][n][r] half: row = 256B = [u 0..63 | v 0..63]

// ---------------------------------------------------------------------------
// Kernel 1 (HMMA): uv[n][r] = sum_c x[c][n] * Wt[c][r]  (+bias for r<64)
//   A = x^T (n x c), col_major  -> smem layout [c][n]  (x's natural layout!)
//   B = Wt  (c x r), row_major  -> smem layout [c][r]  (transform's natural layout)
//   D tile 128n x 128r per block; warp = 16n x 128r (8 n-row warps).
// fp16 inputs, fp32 accumulate; bias+fp16 convert in epilogue.
// ---------------------------------------------------------------------------
__global__ void __launch_bounds__(256) gemm_uv(const float* __restrict__ x,
                                               const float* __restrict__ W,
                                               const float* __restrict__ bias) {
    extern __shared__ char dyn[];
    __half* sA = (__half*)dyn;                       // [C_][LDA]  17,408 B
    __half* sB = (__half*)(dyn + C_ * LDA * 2);      // [C_][LDB]  17,408 B
    float*  sc = (float*)dyn;                        // [NT_][LDS_] 69,632 B (union, after sync)

    const int b  = blockIdx.y;
    const int n0 = blockIdx.x * NT_;
    const int t  = threadIdx.x;
    const int wn = t >> 5;        // warp id = n-tile row (16 nodes each)
    const int lane = t & 31;

    // ---- load x tile: sA[c][nl] = (half)x[b][c][n0+nl]  (coalesced, no transpose)
    for (int lin = t; lin < C_ * NT_; lin += 256) {
        int c  = lin >> 7;
        int nl = lin & (NT_ - 1);
        sA[c * LDA + nl] = __float2half(x[((b * C_ + c) * N_) + n0 + nl]);
    }
    // ---- fused weight transform: sB[c][r] = Wd, sB[c][r+64] = W2  (fp16)
    for (int lin = t; lin < C_ * OUT_; lin += 256) {
        int c = lin & 63;
        int r = lin >> 6;                 // 0..63
        float a  = W[r * 128 + c];        // W1[r][c]
        float bb = W[r * 128 + 64 + c];   // W2[r][c]
        sB[c * LDB + r]      = __float2half(a - bb);
        sB[c * LDB + r + 64] = __float2half(bb);
    }
    __syncthreads();

    // ---- MMA: warp wn computes rows [wn*16, wn*16+16) x 128 r
    wmma::fragment<wmma::matrix_a, 16, 16, 16, __half, wmma::col_major> fa[4];
    #pragma unroll
    for (int k = 0; k < 4; k++)                     // A tile (n=wn*16, c=k*16)
        wmma::load_matrix_sync(fa[k], sA + (k * 16) * LDA + wn * 16, LDA);

    wmma::fragment<wmma::accumulator, 16, 16, 16, float> fc[8];
    #pragma unroll
    for (int rt = 0; rt < 8; rt++) {
        wmma::fill_fragment(fc[rt], 0.0f);
        #pragma unroll
        for (int k = 0; k < 4; k++) {
            wmma::fragment<wmma::matrix_b, 16, 16, 16, __half, wmma::row_major> fb;
            wmma::load_matrix_sync(fb, sB + (k * 16) * LDB + rt * 16, LDB);
            wmma::mma_sync(fc[rt], fa[k], fb, fc[rt]);
        }
    }
    __syncthreads();   // all warps done reading sA/sB before scratch overwrites

    #pragma unroll
    for (int rt = 0; rt < 8; rt++)
        wmma::store_matrix_sync(sc + (wn * 16) * LDS_ + rt * 16, fc[rt],
                                LDS_, wmma::mem_row_major);
    __syncthreads();

    // ---- epilogue: bias (r<64) + fp16 convert + node-major store (256B rows)
    __half* outb = g_uvh + (size_t)(b * N_ + n0) * R_;
    for (int idx = t; idx < NT_ * 64; idx += 256) {   // half2 granularity
        int nl = idx >> 6;
        int rp = idx & 63;                            // half2 index; r = 2*rp, 2*rp+1
        float lo = sc[nl * LDS_ + 2 * rp];
        float hi = sc[nl * LDS_ + 2 * rp + 1];
        if (rp < 32) {                                // u rows get bias
            lo += bias[2 * rp];
            hi += bias[2 * rp + 1];
        }
        *(__half2*)(outb + nl * R_ + 2 * rp) = __floats2half2_rn(lo, hi);
    }
}

// ---------------------------------------------------------------------------
// Kernel 2: out[b][o][n] = max_k relu( u[b][i1(k)][o] + v[b][i0(k)][o] )
// Two nodes per warp; packed-index shfl; LDG.64 gathers; half2 add/max.
// At the L2-bytes roofline (~12-13us) — unchanged.
// ---------------------------------------------------------------------------
__global__ void __launch_bounds__(256) gather_max(const int* __restrict__ edge,
                                                  float* __restrict__ out) {
    __shared__ float sm[OUT_][17];   // 64 x 16 nodes, pad to 17

    const int b    = blockIdx.y;
    const int n0   = blockIdx.x * 16;
    const int w    = threadIdx.x >> 5;
    const int lane = threadIdx.x & 31;
    const int h    = lane >> 4;          // 0 = node A, 1 = node B
    const int sl   = lane & 15;          // sub-lane within node group
    const int n    = n0 + 2 * w + h;

    const int e0 = edge[((0 * B_ + b) * N_ + n) * K_ + sl] & (N_ - 1);   // neighbor -> v
    const int e1 = edge[((1 * B_ + b) * N_ + n) * K_ + sl] & (N_ - 1);   // center   -> u
    const unsigned packed = (unsigned)e0 | ((unsigned)e1 << 16);

    const __half* uvb = g_uvh + (size_t)b * N_ * R_;
    const int co = 4 * sl;               // this lane's channel base (4 channels)

    __half2 m0 = __float2half2_rn(0.0f);
    __half2 m1 = __float2half2_rn(0.0f);

    #pragma unroll
    for (int kk = 0; kk < K_; kk++) {
        unsigned pk = __shfl_sync(0xffffffffu, packed, (h << 4) + kk);
        int i0 = (int)(pk & (unsigned)(N_ - 1));          // v source
        int i1 = (int)((pk >> 16) & (unsigned)(N_ - 1));  // u source
        uint2 uu = *(const uint2*)(uvb + i1 * R_ + co);         // u[co..co+3]
        uint2 vv = *(const uint2*)(uvb + i0 * R_ + 64 + co);    // v[co..co+3]
        __half2 ua = *(__half2*)&uu.x, ub = *(__half2*)&uu.y;
        __half2 va = *(__half2*)&vv.x, vb = *(__half2*)&vv.y;
        m0 = __hmax2(m0, __hadd2(ua, va));
        m1 = __hmax2(m1, __hadd2(ub, vb));
    }

    const int nl = 2 * w + h;
    float2 f0 = __half22float2(m0);
    float2 f1 = __half22float2(m1);
    sm[co + 0][nl] = f0.x;
    sm[co + 1][nl] = f0.y;
    sm[co + 2][nl] = f1.x;
    sm[co + 3][nl] = f1.y;
    __syncthreads();

    const int t = threadIdx.x;
    #pragma unroll
    for (int it = 0; it < 4; it++) {
        int lin = t + it * 256;          // 1024 values: 64 o x 16 n
        int o   = lin >> 4;
        int nn  = lin & 15;
        out[((b * OUT_ + o) * N_) + n0 + nn] = sm[o][nn];
    }
}

// ---------------------------------------------------------------------------
extern "C" void kernel_launch(void* const* d_in, const int* in_sizes, int n_in,
                              void* d_out, int out_size) {
    const float* x    = (const float*)d_in[0];
    const int*   edge = (const int*)d_in[1];
    const float* W    = (const float*)d_in[2];
    const float* bias = (const float*)d_in[3];
    float*       out  = (float*)d_out;

    cudaFuncSetAttribute(gemm_uv, cudaFuncAttributeMaxDynamicSharedMemorySize, SMEM_BYTES);

    dim3 g1(N_ / NT_, B_);
    gemm_uv<<<g1, 256, SMEM_BYTES>>>(x, W, bias);

    dim3 g2(N_ / 16, B_);
    gather_max<<<g2, 256>>>(edge, out);
}

// round 10
// speedup vs baseline: 1.3664x; 1.0055x over previous
#include <cuda_runtime.h>
#include <cuda_fp16.h>
#include <mma.h>

using namespace nvcuda;

// Problem constants
#define B_    8
#define C_    64
#define CP_   80    // padded c: 64 real + 1 bias channel + 15 zero (5 k-tiles of 16)
#define N_    4096
#define K_    16
#define OUT_  64
#define R_    128   // 2*OUT rows: [0,64) = u (=(W1-W2)x + bias), [64,128) = v (=W2 x)

#define NT_   64             // nodes per block tile
#define LDA   72             // sA: half[CP_][LDA]
#define LDB   136            // sB: half[CP_][LDB]
#define LDS_  136            // scratch: float[NT_][LDS_]
#define SA_BYTES (CP_ * LDA * 2)            // 11,520
#define SB_BYTES (CP_ * LDB * 2)            // 21,760
#define SC_BYTES (NT_ * LDS_ * 4)           // 34,816
#define SMEM_BYTES (SC_BYTES)               // scratch unions over sA+sB (33,280)

// Scratch (device global — no allocation allowed)
__device__ __half g_uvh[B_ * N_ * R_];   // [b][n][r] half: row = 256B = [u 0..63 | v 0..63]

// ---------------------------------------------------------------------------
// Kernel 1 (HMMA): uv[n][r] = sum_c x[c][n] * Wt[c][r], bias folded as c=64.
//   A = x^T (n x c) col_major -> smem [c][n] (natural);  c=64 row = 1.0
//   B = Wt (c x r) row_major  -> smem [c][r];            c=64 row = bias|0
// Block: 128 threads (4 warps), tile 64n x 128r; warp = 16n x 128r.
// Grid 512 blocks -> single co-resident wave. fp32 accumulate.
// ---------------------------------------------------------------------------
__global__ void __launch_bounds__(128) gemm_uv(const float* __restrict__ x,
                                               const float* __restrict__ W,
                                               const float* __restrict__ bias) {
    extern __shared__ char dyn[];
    __half* sA = (__half*)dyn;                 // [CP_][LDA]
    __half* sB = (__half*)(dyn + SA_BYTES);    // [CP_][LDB]
    float*  sc = (float*)dyn;                  // [NT_][LDS_] (union, after sync)

    const int b  = blockIdx.y;
    const int n0 = blockIdx.x * NT_;
    const int t  = threadIdx.x;
    const int wn = t >> 5;        // warp id = n-subtile (16 nodes each)

    // ---- sA[c][nl]: x tile (c<64), bias channel (c=64 -> 1.0), zero pad
    for (int lin = t; lin < CP_ * NT_; lin += 128) {
        int c  = lin >> 6;
        int nl = lin & (NT_ - 1);
        float v;
        if (c < 64)       v = x[((b * C_ + c) * N_) + n0 + nl];
        else if (c == 64) v = 1.0f;
        else              v = 0.0f;
        sA[c * LDA + nl] = __float2half(v);
    }
    // ---- sB[c][r]: fused weight transform (c<64)
    for (int lin = t; lin < C_ * OUT_; lin += 128) {
        int c = lin & 63;
        int r = lin >> 6;                 // 0..63
        float a  = W[r * 128 + c];        // W1[r][c]
        float bb = W[r * 128 + 64 + c];   // W2[r][c]
        sB[c * LDB + r]      = __float2half(a - bb);
        sB[c * LDB + r + 64] = __float2half(bb);
    }
    // ---- sB rows 64..79: bias row + zeros
    for (int lin = t; lin < 16 * R_; lin += 128) {
        int c = 64 + (lin >> 7);
        int r = lin & 127;
        float v = (c == 64 && r < 64) ? bias[r] : 0.0f;
        sB[c * LDB + r] = __float2half(v);
    }
    __syncthreads();

    // ---- MMA: warp wn computes rows [wn*16, wn*16+16) x 128 r, 5 k-tiles
    wmma::fragment<wmma::matrix_a, 16, 16, 16, __half, wmma::col_major> fa[5];
    #pragma unroll
    for (int k = 0; k < 5; k++)
        wmma::load_matrix_sync(fa[k], sA + (k * 16) * LDA + wn * 16, LDA);

    wmma::fragment<wmma::accumulator, 16, 16, 16, float> fc[8];
    #pragma unroll
    for (int rt = 0; rt < 8; rt++) {
        wmma::fill_fragment(fc[rt], 0.0f);
        #pragma unroll
        for (int k = 0; k < 5; k++) {
            wmma::fragment<wmma::matrix_b, 16, 16, 16, __half, wmma::row_major> fb;
            wmma::load_matrix_sync(fb, sB + (k * 16) * LDB + rt * 16, LDB);
            wmma::mma_sync(fc[rt], fa[k], fb, fc[rt]);
        }
    }
    __syncthreads();   // all warps done with sA/sB before scratch overwrite

    #pragma unroll
    for (int rt = 0; rt < 8; rt++)
        wmma::store_matrix_sync(sc + (wn * 16) * LDS_ + rt * 16, fc[rt],
                                LDS_, wmma::mem_row_major);
    __syncthreads();

    // ---- epilogue: pure fp16 convert + node-major store (bias already in)
    __half* outb = g_uvh + (size_t)(b * N_ + n0) * R_;
    for (int idx = t; idx < NT_ * 64; idx += 128) {   // half2 granularity
        int nl = idx >> 6;
        int rp = idx & 63;
        float lo = sc[nl * LDS_ + 2 * rp];
        float hi = sc[nl * LDS_ + 2 * rp + 1];
        *(__half2*)(outb + nl * R_ + 2 * rp) = __floats2half2_rn(lo, hi);
    }
}

// ---------------------------------------------------------------------------
// Kernel 2: out[b][o][n] = max_k relu( u[b][i1(k)][o] + v[b][i0(k)][o] )
// FOUR nodes per warp: lane = (h, sl), h = lane>>3 node slot, sl = lane&7.
// Lane covers 8 channels (16B) via LDG.128; indices staged in padded smem,
// read per kk as one LDS.64 int2 broadcast. 32 nodes per 256-thread block.
// ---------------------------------------------------------------------------
__global__ void __launch_bounds__(256) gather_max(const int* __restrict__ edge,
                                                  float* __restrict__ out) {
    __shared__ int2  sIdx[32][17];   // [node_local][k] (i0,i1); pad 16->17 bank-clean
    __shared__ float sm[OUT_][33];   // transpose stage, pad 32->33

    const int b  = blockIdx.y;
    const int n0 = blockIdx.x * 32;
    const int t  = threadIdx.x;

    // Stage indices: 512 (node,k) pairs, both directions, coalesced reads.
    for (int lin = t; lin < 512; lin += 256) {
        int node = lin >> 4;
        int kk   = lin & 15;
        int e0 = edge[((0 * B_ + b) * N_ + n0 + node) * K_ + kk] & (N_ - 1); // neighbor -> v
        int e1 = edge[((1 * B_ + b) * N_ + n0 + node) * K_ + kk] & (N_ - 1); // center   -> u
        sIdx[node][kk] = make_int2(e0, e1);
    }
    __syncthreads();

    const int w    = t >> 5;
    const int lane = t & 31;
    const int h    = lane >> 3;          // node slot 0..3
    const int sl   = lane & 7;           // channel group: halves [8*sl, 8*sl+8)
    const int nl   = 4 * w + h;          // node local 0..31

    const __half* uvb = g_uvh + (size_t)b * N_ * R_;
    const int co = 8 * sl;               // half offset of this lane's channels

    __half2 m0 = __float2half2_rn(0.0f);
    __half2 m1 = m0, m2 = m0, m3 = m0;

    #pragma unroll
    for (int kk = 0; kk < K_; kk++) {
        int2 p = sIdx[nl][kk];           // broadcast within 8-lane group
        uint4 uu = *(const uint4*)(uvb + p.y * R_ + co);        // u[co..co+7]
        uint4 vv = *(const uint4*)(uvb + p.x * R_ + 64 + co);   // v[co..co+7]
        m0 = __hmax2(m0, __hadd2(*(__half2*)&uu.x, *(__half2*)&vv.x));
        m1 = __hmax2(m1, __hadd2(*(__half2*)&uu.y, *(__half2*)&vv.y));
        m2 = __hmax2(m2, __hadd2(*(__half2*)&uu.z, *(__half2*)&vv.z));
        m3 = __hmax2(m3, __hadd2(*(__half2*)&uu.w, *(__half2*)&vv.w));
    }

    // Transpose stage: lane owns channels co..co+7 of node nl.
    float2 f;
    f = __half22float2(m0); sm[co + 0][nl] = f.x; sm[co + 1][nl] = f.y;
    f = __half22float2(m1); sm[co + 2][nl] = f.x; sm[co + 3][nl] = f.y;
    f = __half22float2(m2); sm[co + 4][nl] = f.x; sm[co + 5][nl] = f.y;
    f = __half22float2(m3); sm[co + 6][nl] = f.x; sm[co + 7][nl] = f.y;
    __syncthreads();

    #pragma unroll
    for (int it = 0; it < 8; it++) {
        int lin = t + it * 256;          // 2048 values: 64 o x 32 n
        int o   = lin >> 5;
        int nn  = lin & 31;
        out[((b * OUT_ + o) * N_) + n0 + nn] = sm[o][nn];
    }
}

// ---------------------------------------------------------------------------
extern "C" void kernel_launch(void* const* d_in, const int* in_sizes, int n_in,
                              void* d_out, int out_size) {
    const float* x    = (const float*)d_in[0];
    const int*   edge = (const int*)d_in[1];
    const float* W    = (const float*)d_in[2];
    const float* bias = (const float*)d_in[3];
    float*       out  = (float*)d_out;

    cudaFuncSetAttribute(gemm_uv, cudaFuncAttributeMaxDynamicSharedMemorySize, SMEM_BYTES);

    dim3 g1(N_ / NT_, B_);
    gemm_uv<<<g1, 128, SMEM_BYTES>>>(x, W, bias);

    dim3 g2(N_ / 32, B_);
    gather_max<<<g2, 256>>>(edge, out);
}